// round 1
// baseline (speedup 1.0000x reference)
#include <cuda_runtime.h>
#include <cuda_bf16.h>

#define N_NODES 50000
#define N_EDGES 800000

// ---------------- scratch (static device globals; no allocation) ----------------
__device__ float g_deg[N_NODES];
__device__ float g_dinv[N_NODES];
__device__ int   g_hist[N_NODES];
__device__ int   g_rowoff[N_NODES + 1];
__device__ int   g_cursor[N_NODES];
__device__ int   g_ecol[N_EDGES];
__device__ float g_elw[N_EDGES];
__device__ float g_U[N_NODES * 256];   // [Z0 | U1 | R0 | U2]
__device__ float g_V[N_NODES * 128];   // [H0 | U3]
__device__ float g_zb[N_NODES * 64];
__device__ float g_rhb[N_NODES * 64];
__device__ int   g_is64;

// ---------------- helpers ----------------
__device__ __forceinline__ int edge_idx(const void* ei, int pos) {
    if (g_is64) return (int)((const long long*)ei)[pos];
    return ((const int*)ei)[pos];
}

// ---------------- kernel 1: zero accumulators + sniff index dtype ----------------
__global__ void k_init(const void* ei) {
    int i = blockIdx.x * blockDim.x + threadIdx.x;
    if (i < N_NODES) { g_deg[i] = 0.f; g_hist[i] = 0; }
    if (i == 0) {
        // If the buffer is int64, values < 2^31 mean every odd 32-bit word is 0.
        // Random int32 node ids make "all 256 odd words zero" impossible.
        const int* p = (const int*)ei;
        int nz = 0;
#pragma unroll 8
        for (int j = 0; j < 256; j++) nz |= p[2 * j + 1];
        g_is64 = (nz == 0) ? 1 : 0;
    }
}

// ---------------- kernel 2: degree + histogram ----------------
__global__ void k_deg(const void* ei, const float* __restrict__ w) {
    int e = blockIdx.x * blockDim.x + threadIdx.x;
    if (e >= N_EDGES) return;
    int r = edge_idx(ei, e);
    atomicAdd(&g_deg[r], w[e]);
    atomicAdd(&g_hist[r], 1);
}

// ---------------- kernel 3: dinv ----------------
__global__ void k_dinv() {
    int i = blockIdx.x * blockDim.x + threadIdx.x;
    if (i >= N_NODES) return;
    float d = g_deg[i];
    g_dinv[i] = (d > 0.f) ? rsqrtf(d) : 0.f;
}

// ---------------- kernel 4: single-block exclusive scan of hist -> rowoff ----------------
__global__ void k_scan() {
    __shared__ int ssum[1024];
    const int CH = (N_NODES + 1023) / 1024;  // 49
    int t = threadIdx.x;
    int base = t * CH;
    int s = 0;
    for (int j = 0; j < CH; j++) { int i = base + j; if (i < N_NODES) s += g_hist[i]; }
    ssum[t] = s;
    __syncthreads();
    for (int off = 1; off < 1024; off <<= 1) {
        int v = (t >= off) ? ssum[t - off] : 0;
        __syncthreads();
        ssum[t] += v;
        __syncthreads();
    }
    int run = (t == 0) ? 0 : ssum[t - 1];
    for (int j = 0; j < CH; j++) {
        int i = base + j;
        if (i < N_NODES) { g_rowoff[i] = run; g_cursor[i] = run; run += g_hist[i]; }
    }
    if (t == 1023) g_rowoff[N_NODES] = ssum[1023];
}

// ---------------- kernel 5: CSR scatter + normalized edge weights ----------------
__global__ void k_csr(const void* ei, const float* __restrict__ w) {
    int e = blockIdx.x * blockDim.x + threadIdx.x;
    if (e >= N_EDGES) return;
    int r = edge_idx(ei, e);
    int c = edge_idx(ei, N_EDGES + e);
    int p = atomicAdd(&g_cursor[r], 1);
    g_ecol[p] = c;
    // lambda_max=2: lw = -(2/2) * w * dinv[r] * dinv[c]; diagonal term is 0.
    g_elw[p] = -w[e] * g_dinv[r] * g_dinv[c];
}

// ---------------- GEMM: [N,128] x [128, 64*gridDim.y] -> C, A = [src0 | src1] ----------------
// dst_sel: 0 -> g_U (ldc=256), 1 -> g_V (ldc=128). use_rhb: src1 = g_rhb.
__global__ void __launch_bounds__(256) k_gemm(
    const float* __restrict__ src0, const float* __restrict__ src1_ext, int use_rhb,
    const float* __restrict__ B0, const float* __restrict__ B1,
    const float* __restrict__ B2, const float* __restrict__ B3,
    int dst_sel, int ldc) {
    __shared__ float As[64][65];   // [k][m], padded
    __shared__ float Bs[64][64];   // [k][n]

    int t = threadIdx.x;
    int tx = t & 15, ty = t >> 4;
    int rowBase = blockIdx.x * 64;
    const float* Bsel = (blockIdx.y == 0) ? B0 : (blockIdx.y == 1) ? B1
                      : (blockIdx.y == 2) ? B2 : B3;
    float* C = dst_sel ? g_V : g_U;
    const float* src1 = use_rhb ? g_rhb : src1_ext;

    float acc[4][4] = {};
    for (int kc = 0; kc < 2; kc++) {
        const float* A = kc ? src1 : src0;
#pragma unroll
        for (int i = 0; i < 4; i++) {
            int f = t + i * 256;         // 0..1023
            int m = f >> 4;              // 0..63
            int k4 = (f & 15) << 2;      // 0..60
            int r = rowBase + m;
            float4 v = make_float4(0.f, 0.f, 0.f, 0.f);
            if (r < N_NODES) v = *(const float4*)&A[r * 64 + k4];
            As[k4 + 0][m] = v.x; As[k4 + 1][m] = v.y;
            As[k4 + 2][m] = v.z; As[k4 + 3][m] = v.w;
        }
#pragma unroll
        for (int i = 0; i < 4; i++) {
            int f = t + i * 256;
            int k = f >> 4;
            int n4 = (f & 15) << 2;
            *(float4*)&Bs[k][n4] = *(const float4*)&Bsel[(kc * 64 + k) * 64 + n4];
        }
        __syncthreads();
#pragma unroll 8
        for (int k = 0; k < 64; k++) {
            float a0 = As[k][(ty << 2) + 0];
            float a1 = As[k][(ty << 2) + 1];
            float a2 = As[k][(ty << 2) + 2];
            float a3 = As[k][(ty << 2) + 3];
            float4 b = *(const float4*)&Bs[k][tx << 2];
            acc[0][0] += a0 * b.x; acc[0][1] += a0 * b.y; acc[0][2] += a0 * b.z; acc[0][3] += a0 * b.w;
            acc[1][0] += a1 * b.x; acc[1][1] += a1 * b.y; acc[1][2] += a1 * b.z; acc[1][3] += a1 * b.w;
            acc[2][0] += a2 * b.x; acc[2][1] += a2 * b.y; acc[2][2] += a2 * b.z; acc[2][3] += a2 * b.w;
            acc[3][0] += a3 * b.x; acc[3][1] += a3 * b.y; acc[3][2] += a3 * b.z; acc[3][3] += a3 * b.w;
        }
        __syncthreads();
    }
    int colBase = blockIdx.y * 64 + (tx << 2);
#pragma unroll
    for (int i = 0; i < 4; i++) {
        int r = rowBase + (ty << 2) + i;
        if (r < N_NODES)
            *(float4*)&C[r * ldc + colBase] =
                make_float4(acc[i][0], acc[i][1], acc[i][2], acc[i][3]);
    }
}

// ---------------- prop1: warp/row over CSR, 128 gathered channels; fused gates ----------------
__global__ void k_prop1(const float* __restrict__ h,
                        const float* __restrict__ bz, const float* __restrict__ br) {
    int gw = (blockIdx.x * blockDim.x + threadIdx.x) >> 5;
    int lane = threadIdx.x & 31;
    if (gw >= N_NODES) return;
    int s = g_rowoff[gw], e = g_rowoff[gw + 1];
    int co = lane * 2;
    float a1x = 0.f, a1y = 0.f, a2x = 0.f, a2y = 0.f;
    for (int i = s; i < e; i++) {
        int c = g_ecol[i];
        float w = g_elw[i];
        const float* up = &g_U[c * 256 + co];
        float2 u1 = *(const float2*)(up + 64);
        float2 u2 = *(const float2*)(up + 192);
        a1x += w * u1.x; a1y += w * u1.y;
        a2x += w * u2.x; a2y += w * u2.y;
    }
    const float* rowp = &g_U[gw * 256 + co];
    float2 z0 = *(const float2*)(rowp);
    float2 r0 = *(const float2*)(rowp + 128);
    float2 bz2 = *(const float2*)&bz[co];
    float2 br2 = *(const float2*)&br[co];
    float zx = 1.f / (1.f + __expf(-(z0.x + bz2.x + a1x)));
    float zy = 1.f / (1.f + __expf(-(z0.y + bz2.y + a1y)));
    float rx = 1.f / (1.f + __expf(-(r0.x + br2.x + a2x)));
    float ry = 1.f / (1.f + __expf(-(r0.y + br2.y + a2y)));
    float2 hh = *(const float2*)&h[gw * 64 + co];
    *(float2*)&g_zb[gw * 64 + co] = make_float2(zx, zy);
    *(float2*)&g_rhb[gw * 64 + co] = make_float2(rx * hh.x, ry * hh.y);
}

// ---------------- prop2: 64 gathered channels; fused tanh + GRU update ----------------
__global__ void k_prop2(const float* __restrict__ h, const float* __restrict__ bh,
                        float* __restrict__ out) {
    int gw = (blockIdx.x * blockDim.x + threadIdx.x) >> 5;
    int lane = threadIdx.x & 31;
    if (gw >= N_NODES) return;
    int s = g_rowoff[gw], e = g_rowoff[gw + 1];
    int co = lane * 2;
    float ax = 0.f, ay = 0.f;
    for (int i = s; i < e; i++) {
        int c = g_ecol[i];
        float w = g_elw[i];
        float2 u = *(const float2*)&g_V[c * 128 + 64 + co];
        ax += w * u.x; ay += w * u.y;
    }
    float2 h0 = *(const float2*)&g_V[gw * 128 + co];
    float2 bh2 = *(const float2*)&bh[co];
    float htx = tanhf(h0.x + bh2.x + ax);
    float hty = tanhf(h0.y + bh2.y + ay);
    float2 z = *(const float2*)&g_zb[gw * 64 + co];
    float2 hh = *(const float2*)&h[gw * 64 + co];
    float ox = (1.f - z.x) * hh.x + z.x * htx;
    float oy = (1.f - z.y) * hh.y + z.y * hty;
    *(float2*)&out[gw * 64 + co] = make_float2(ox, oy);
}

// ---------------- launch ----------------
extern "C" void kernel_launch(void* const* d_in, const int* in_sizes, int n_in,
                              void* d_out, int out_size) {
    const float* x  = (const float*)d_in[0];
    const void*  ei = d_in[1];
    const float* ew = (const float*)d_in[2];
    const float* h  = (const float*)d_in[3];
    const float* Wz = (const float*)d_in[4];
    const float* bz = (const float*)d_in[5];
    const float* Wr = (const float*)d_in[6];
    const float* br = (const float*)d_in[7];
    const float* Wh = (const float*)d_in[8];
    const float* bh = (const float*)d_in[9];
    float* out = (float*)d_out;

    const int TB = 256;
    const int nb_nodes = (N_NODES + TB - 1) / TB;
    const int nb_edges = (N_EDGES + TB - 1) / TB;
    const int nb_rows  = (N_NODES + 7) / 8;        // 8 warps/block, 1 warp/row
    const int nb_gemm  = (N_NODES + 63) / 64;

    k_init<<<nb_nodes, TB>>>(ei);
    k_deg<<<nb_edges, TB>>>(ei, ew);
    k_dinv<<<nb_nodes, TB>>>();
    k_scan<<<1, 1024>>>();
    k_csr<<<nb_edges, TB>>>(ei, ew);

    // GEMM1: [x|h] @ [Wz0 | Wz1 | Wr0 | Wr1] -> g_U [N,256]
    k_gemm<<<dim3(nb_gemm, 4), TB>>>(x, h, 0,
                                     Wz, Wz + 8192, Wr, Wr + 8192,
                                     /*dst_sel=*/0, /*ldc=*/256);
    k_prop1<<<nb_rows, TB>>>(h, bz, br);

    // GEMM2: [x|r*h] @ [Wh0 | Wh1] -> g_V [N,128]
    k_gemm<<<dim3(nb_gemm, 2), TB>>>(x, nullptr, 1,
                                     Wh, Wh + 8192, Wh, Wh,
                                     /*dst_sel=*/1, /*ldc=*/128);
    k_prop2<<<nb_rows, TB>>>(h, bh, out);
}

// round 2
// speedup vs baseline: 1.2452x; 1.2452x over previous
#include <cuda_runtime.h>
#include <cuda_bf16.h>

#define N_NODES 50000
#define N_EDGES 800000

// ---------------- scratch (static device globals; no allocation) ----------------
__device__ float g_deg[N_NODES];
__device__ float g_dinv[N_NODES];
__device__ int   g_hist[N_NODES];
__device__ int   g_rowoff[N_NODES];
__device__ int   g_rowend[N_NODES];
__device__ int   g_cursor[N_NODES];
__device__ int   g_ecol[N_EDGES];
__device__ float g_elw[N_EDGES];
__device__ float g_U[N_NODES * 256];   // [Z0 | U1 | R0 | U2]
__device__ float g_V[N_NODES * 128];   // [H0 | U3]
__device__ float g_zb[N_NODES * 64];
__device__ float g_rhb[N_NODES * 64];
__device__ int   g_is64;
__device__ int   g_counter;

// ---------------- helpers ----------------
__device__ __forceinline__ int edge_idx(const void* ei, int pos) {
    if (g_is64) return (int)((const long long*)ei)[pos];
    return ((const int*)ei)[pos];
}

// ---------------- kernel 1: zero accumulators + sniff index dtype ----------------
__global__ void k_init(const void* ei) {
    int i = blockIdx.x * blockDim.x + threadIdx.x;
    if (i < N_NODES) { g_deg[i] = 0.f; g_hist[i] = 0; }
    if (i == 0) {
        g_counter = 0;
        // If the buffer is int64, values < 2^31 mean every odd 32-bit word is 0.
        // Random int32 node ids make "all 256 odd words zero" impossible.
        const int* p = (const int*)ei;
        int nz = 0;
#pragma unroll 8
        for (int j = 0; j < 256; j++) nz |= p[2 * j + 1];
        g_is64 = (nz == 0) ? 1 : 0;
    }
}

// ---------------- kernel 2: degree + histogram ----------------
__global__ void k_deg(const void* ei, const float* __restrict__ w) {
    int e = blockIdx.x * blockDim.x + threadIdx.x;
    if (e >= N_EDGES) return;
    int r = edge_idx(ei, e);
    atomicAdd(&g_deg[r], w[e]);
    atomicAdd(&g_hist[r], 1);
}

// ---------------- kernel 3: dinv ----------------
__global__ void k_dinv() {
    int i = blockIdx.x * blockDim.x + threadIdx.x;
    if (i >= N_NODES) return;
    float d = g_deg[i];
    g_dinv[i] = (d > 0.f) ? rsqrtf(d) : 0.f;
}

// ---------------- kernel 4: unordered segment assignment ----------------
// CSR segments need only be contiguous and disjoint, NOT row-ordered.
// Per-block exclusive scan (shuffles) + one atomicAdd for the block base.
__global__ void k_blockscan() {
    int i = blockIdx.x * 256 + threadIdx.x;
    int lane = threadIdx.x & 31, w = threadIdx.x >> 5;
    int v = (i < N_NODES) ? g_hist[i] : 0;
    int s = v;
#pragma unroll
    for (int o = 1; o < 32; o <<= 1) {
        int t = __shfl_up_sync(0xFFFFFFFFu, s, o);
        if (lane >= o) s += t;
    }
    __shared__ int wsum[8];
    __shared__ int base;
    if (lane == 31) wsum[w] = s;
    __syncthreads();
    if (w == 0 && lane < 8) {
        int t = wsum[lane];
#pragma unroll
        for (int o = 1; o < 8; o <<= 1) {
            int u = __shfl_up_sync(0xFFu, t, o);
            if (lane >= o) t += u;
        }
        wsum[lane] = t;
        if (lane == 7) base = atomicAdd(&g_counter, t);
    }
    __syncthreads();
    int excl = s - v + ((w > 0) ? wsum[w - 1] : 0);
    if (i < N_NODES) {
        int st = base + excl;
        g_rowoff[i] = st;
        g_cursor[i] = st;
        g_rowend[i] = st + v;
    }
}

// ---------------- kernel 5: CSR scatter + normalized edge weights ----------------
__global__ void k_csr(const void* ei, const float* __restrict__ w) {
    int e = blockIdx.x * blockDim.x + threadIdx.x;
    if (e >= N_EDGES) return;
    int r = edge_idx(ei, e);
    int c = edge_idx(ei, N_EDGES + e);
    int p = atomicAdd(&g_cursor[r], 1);
    g_ecol[p] = c;
    // lambda_max=2: lw = -(2/2) * w * dinv[r] * dinv[c]; diagonal term is 0.
    g_elw[p] = -w[e] * g_dinv[r] * g_dinv[c];
}

// ---------------- GEMM: [N,128] x [128, 64*gridDim.y] -> C, A = [src0 | src1] ----------------
// dst_sel: 0 -> g_U (ldc=256), 1 -> g_V (ldc=128). use_rhb: src1 = g_rhb.
__global__ void __launch_bounds__(256) k_gemm(
    const float* __restrict__ src0, const float* __restrict__ src1_ext, int use_rhb,
    const float* __restrict__ B0, const float* __restrict__ B1,
    const float* __restrict__ B2, const float* __restrict__ B3,
    int dst_sel, int ldc) {
    __shared__ float As[64][68];   // [k][m], pad 68 keeps float4 rows 16B-aligned
    __shared__ float Bs[64][64];   // [k][n]

    int t = threadIdx.x;
    int tx = t & 15, ty = t >> 4;
    int rowBase = blockIdx.x * 64;
    const float* Bsel = (blockIdx.y == 0) ? B0 : (blockIdx.y == 1) ? B1
                      : (blockIdx.y == 2) ? B2 : B3;
    float* C = dst_sel ? g_V : g_U;
    const float* src1 = use_rhb ? g_rhb : src1_ext;

    float acc[4][4] = {};
    for (int kc = 0; kc < 2; kc++) {
        const float* A = kc ? src1 : src0;
#pragma unroll
        for (int i = 0; i < 4; i++) {
            int f = t + i * 256;         // 0..1023
            int m = f >> 4;              // 0..63
            int k4 = (f & 15) << 2;      // 0..60
            int r = rowBase + m;
            float4 v = make_float4(0.f, 0.f, 0.f, 0.f);
            if (r < N_NODES) v = *(const float4*)&A[r * 64 + k4];
            As[k4 + 0][m] = v.x; As[k4 + 1][m] = v.y;
            As[k4 + 2][m] = v.z; As[k4 + 3][m] = v.w;
        }
#pragma unroll
        for (int i = 0; i < 4; i++) {
            int f = t + i * 256;
            int k = f >> 4;
            int n4 = (f & 15) << 2;
            *(float4*)&Bs[k][n4] = *(const float4*)&Bsel[(kc * 64 + k) * 64 + n4];
        }
        __syncthreads();
#pragma unroll 8
        for (int k = 0; k < 64; k++) {
            float4 a = *(const float4*)&As[k][ty << 2];
            float4 b = *(const float4*)&Bs[k][tx << 2];
            acc[0][0] += a.x * b.x; acc[0][1] += a.x * b.y; acc[0][2] += a.x * b.z; acc[0][3] += a.x * b.w;
            acc[1][0] += a.y * b.x; acc[1][1] += a.y * b.y; acc[1][2] += a.y * b.z; acc[1][3] += a.y * b.w;
            acc[2][0] += a.z * b.x; acc[2][1] += a.z * b.y; acc[2][2] += a.z * b.z; acc[2][3] += a.z * b.w;
            acc[3][0] += a.w * b.x; acc[3][1] += a.w * b.y; acc[3][2] += a.w * b.z; acc[3][3] += a.w * b.w;
        }
        __syncthreads();
    }
    int colBase = blockIdx.y * 64 + (tx << 2);
#pragma unroll
    for (int i = 0; i < 4; i++) {
        int r = rowBase + (ty << 2) + i;
        if (r < N_NODES)
            *(float4*)&C[r * ldc + colBase] =
                make_float4(acc[i][0], acc[i][1], acc[i][2], acc[i][3]);
    }
}

// ---------------- prop1: warp/row over CSR, 128 gathered channels; fused gates ----------------
__global__ void k_prop1(const float* __restrict__ h,
                        const float* __restrict__ bz, const float* __restrict__ br) {
    int gw = (blockIdx.x * blockDim.x + threadIdx.x) >> 5;
    int lane = threadIdx.x & 31;
    if (gw >= N_NODES) return;
    int s = g_rowoff[gw], e = g_rowend[gw];
    int co = lane * 2;
    float a1x = 0.f, a1y = 0.f, a2x = 0.f, a2y = 0.f;
    for (int i = s; i < e; i++) {
        int c = g_ecol[i];
        float w = g_elw[i];
        const float* up = &g_U[c * 256 + co];
        float2 u1 = *(const float2*)(up + 64);
        float2 u2 = *(const float2*)(up + 192);
        a1x += w * u1.x; a1y += w * u1.y;
        a2x += w * u2.x; a2y += w * u2.y;
    }
    const float* rowp = &g_U[gw * 256 + co];
    float2 z0 = *(const float2*)(rowp);
    float2 r0 = *(const float2*)(rowp + 128);
    float2 bz2 = *(const float2*)&bz[co];
    float2 br2 = *(const float2*)&br[co];
    float zx = 1.f / (1.f + __expf(-(z0.x + bz2.x + a1x)));
    float zy = 1.f / (1.f + __expf(-(z0.y + bz2.y + a1y)));
    float rx = 1.f / (1.f + __expf(-(r0.x + br2.x + a2x)));
    float ry = 1.f / (1.f + __expf(-(r0.y + br2.y + a2y)));
    float2 hh = *(const float2*)&h[gw * 64 + co];
    *(float2*)&g_zb[gw * 64 + co] = make_float2(zx, zy);
    *(float2*)&g_rhb[gw * 64 + co] = make_float2(rx * hh.x, ry * hh.y);
}

// ---------------- prop2: 64 gathered channels; fused tanh + GRU update ----------------
__global__ void k_prop2(const float* __restrict__ h, const float* __restrict__ bh,
                        float* __restrict__ out) {
    int gw = (blockIdx.x * blockDim.x + threadIdx.x) >> 5;
    int lane = threadIdx.x & 31;
    if (gw >= N_NODES) return;
    int s = g_rowoff[gw], e = g_rowend[gw];
    int co = lane * 2;
    float ax = 0.f, ay = 0.f;
    for (int i = s; i < e; i++) {
        int c = g_ecol[i];
        float w = g_elw[i];
        float2 u = *(const float2*)&g_V[c * 128 + 64 + co];
        ax += w * u.x; ay += w * u.y;
    }
    float2 h0 = *(const float2*)&g_V[gw * 128 + co];
    float2 bh2 = *(const float2*)&bh[co];
    float htx = tanhf(h0.x + bh2.x + ax);
    float hty = tanhf(h0.y + bh2.y + ay);
    float2 z = *(const float2*)&g_zb[gw * 64 + co];
    float2 hh = *(const float2*)&h[gw * 64 + co];
    float ox = (1.f - z.x) * hh.x + z.x * htx;
    float oy = (1.f - z.y) * hh.y + z.y * hty;
    *(float2*)&out[gw * 64 + co] = make_float2(ox, oy);
}

// ---------------- launch ----------------
extern "C" void kernel_launch(void* const* d_in, const int* in_sizes, int n_in,
                              void* d_out, int out_size) {
    const float* x  = (const float*)d_in[0];
    const void*  ei = d_in[1];
    const float* ew = (const float*)d_in[2];
    const float* h  = (const float*)d_in[3];
    const float* Wz = (const float*)d_in[4];
    const float* bz = (const float*)d_in[5];
    const float* Wr = (const float*)d_in[6];
    const float* br = (const float*)d_in[7];
    const float* Wh = (const float*)d_in[8];
    const float* bh = (const float*)d_in[9];
    float* out = (float*)d_out;

    const int TB = 256;
    const int nb_nodes = (N_NODES + TB - 1) / TB;
    const int nb_edges = (N_EDGES + TB - 1) / TB;
    const int nb_rows  = (N_NODES + 7) / 8;        // 8 warps/block, 1 warp/row
    const int nb_gemm  = (N_NODES + 63) / 64;

    k_init<<<nb_nodes, TB>>>(ei);
    k_deg<<<nb_edges, TB>>>(ei, ew);
    k_dinv<<<nb_nodes, TB>>>();
    k_blockscan<<<nb_nodes, TB>>>();
    k_csr<<<nb_edges, TB>>>(ei, ew);

    // GEMM1: [x|h] @ [Wz0 | Wz1 | Wr0 | Wr1] -> g_U [N,256]
    k_gemm<<<dim3(nb_gemm, 4), TB>>>(x, h, 0,
                                     Wz, Wz + 8192, Wr, Wr + 8192,
                                     /*dst_sel=*/0, /*ldc=*/256);
    k_prop1<<<nb_rows, TB>>>(h, bz, br);

    // GEMM2: [x|r*h] @ [Wh0 | Wh1] -> g_V [N,128]
    k_gemm<<<dim3(nb_gemm, 2), TB>>>(x, nullptr, 1,
                                     Wh, Wh + 8192, Wh, Wh,
                                     /*dst_sel=*/1, /*ldc=*/128);
    k_prop2<<<nb_rows, TB>>>(h, bh, out);
}

// round 4
// speedup vs baseline: 1.7329x; 1.3916x over previous
#include <cuda_runtime.h>
#include <cuda_bf16.h>
#include <cstdint>

#define N_NODES 50000
#define N_EDGES 800000

// ---------------- scratch (static device globals; no allocation) ----------------
__device__ float g_deg[N_NODES];
__device__ float g_dinv[N_NODES];
__device__ int   g_hist[N_NODES];
__device__ int   g_rowoff[N_NODES];
__device__ int   g_rowend[N_NODES];
__device__ int   g_cursor[N_NODES];
__device__ int   g_ecol[N_EDGES];
__device__ float g_elw[N_EDGES];
__device__ float g_U[N_NODES * 256];   // [Z0 | U1 | R0 | U2]
__device__ float g_V[N_NODES * 128];   // [H0 | U3]
__device__ float g_zb[N_NODES * 64];
__device__ float g_rhb[N_NODES * 64];
__device__ __nv_bfloat16 g_Wbhi[6 * 64 * 128];  // [mat][n][k] transposed weights, bf16 hi
__device__ __nv_bfloat16 g_Wblo[6 * 64 * 128];  // bf16 residual
__device__ int   g_is64;
__device__ int   g_counter;

// ---------------- helpers ----------------
__device__ __forceinline__ uint32_t smem_u32(const void* p) {
    uint32_t a;
    asm("{ .reg .u64 t; cvta.to.shared.u64 t, %1; cvt.u32.u64 %0, t; }" : "=r"(a) : "l"(p));
    return a;
}
__device__ __forceinline__ uint32_t pack_bf16x2(float lo, float hi) {
    __nv_bfloat162 t = __floats2bfloat162_rn(lo, hi);
    return *(uint32_t*)&t;
}
__device__ __forceinline__ void ldsm4(uint32_t a[4], uint32_t addr) {
    asm volatile("ldmatrix.sync.aligned.m8n8.x4.shared.b16 {%0,%1,%2,%3}, [%4];"
                 : "=r"(a[0]), "=r"(a[1]), "=r"(a[2]), "=r"(a[3]) : "r"(addr));
}
__device__ __forceinline__ void mma_bf16(float c[4], const uint32_t a[4], const uint32_t b[2]) {
    asm volatile("mma.sync.aligned.m16n8k16.row.col.f32.bf16.bf16.f32 "
                 "{%0,%1,%2,%3}, {%4,%5,%6,%7}, {%8,%9}, {%0,%1,%2,%3};"
                 : "+f"(c[0]), "+f"(c[1]), "+f"(c[2]), "+f"(c[3])
                 : "r"(a[0]), "r"(a[1]), "r"(a[2]), "r"(a[3]), "r"(b[0]), "r"(b[1]));
}
__device__ __forceinline__ int edge_idx(const void* ei, int pos) {
    if (g_is64) return (int)((const long long*)ei)[pos];
    return ((const int*)ei)[pos];
}

// ---------------- kernel 1: zero accumulators + sniff index dtype ----------------
__global__ void k_init(const void* ei) {
    int i = blockIdx.x * blockDim.x + threadIdx.x;
    if (i < N_NODES) { g_deg[i] = 0.f; g_hist[i] = 0; }
    if (i == 0) {
        g_counter = 0;
        const int* p = (const int*)ei;
        int nz = 0;
#pragma unroll 8
        for (int j = 0; j < 256; j++) nz |= p[2 * j + 1];
        g_is64 = (nz == 0) ? 1 : 0;
    }
}

// ---------------- weight prep: transpose + split to bf16 hi/lo ----------------
__global__ void k_wprep(const float* __restrict__ Wz, const float* __restrict__ Wr,
                        const float* __restrict__ Wh) {
    int id = blockIdx.x * 256 + threadIdx.x;
    if (id >= 6 * 8192) return;
    int m = id >> 13;
    int r = id & 8191;
    int n = r >> 7;
    int k = r & 127;
    const float* W = (m < 2) ? Wz : (m < 4) ? Wr : Wh;
    float v = W[(m & 1) * 8192 + k * 64 + n];
    __nv_bfloat16 hi = __float2bfloat16(v);
    g_Wbhi[id] = hi;
    g_Wblo[id] = __float2bfloat16(v - __bfloat162float(hi));
}

// ---------------- kernel 2: degree + histogram ----------------
__global__ void k_deg(const void* ei, const float* __restrict__ w) {
    int e = blockIdx.x * blockDim.x + threadIdx.x;
    if (e >= N_EDGES) return;
    int r = edge_idx(ei, e);
    atomicAdd(&g_deg[r], w[e]);
    atomicAdd(&g_hist[r], 1);
}

// ---------------- kernel 3: dinv ----------------
__global__ void k_dinv() {
    int i = blockIdx.x * blockDim.x + threadIdx.x;
    if (i >= N_NODES) return;
    float d = g_deg[i];
    g_dinv[i] = (d > 0.f) ? rsqrtf(d) : 0.f;
}

// ---------------- kernel 4: unordered segment assignment ----------------
__global__ void k_blockscan() {
    int i = blockIdx.x * 256 + threadIdx.x;
    int lane = threadIdx.x & 31, w = threadIdx.x >> 5;
    int v = (i < N_NODES) ? g_hist[i] : 0;
    int s = v;
#pragma unroll
    for (int o = 1; o < 32; o <<= 1) {
        int t = __shfl_up_sync(0xFFFFFFFFu, s, o);
        if (lane >= o) s += t;
    }
    __shared__ int wsum[8];
    __shared__ int base;
    if (lane == 31) wsum[w] = s;
    __syncthreads();
    if (w == 0 && lane < 8) {
        int t = wsum[lane];
#pragma unroll
        for (int o = 1; o < 8; o <<= 1) {
            int u = __shfl_up_sync(0xFFu, t, o);
            if (lane >= o) t += u;
        }
        wsum[lane] = t;
        if (lane == 7) base = atomicAdd(&g_counter, t);
    }
    __syncthreads();
    int excl = s - v + ((w > 0) ? wsum[w - 1] : 0);
    if (i < N_NODES) {
        int st = base + excl;
        g_rowoff[i] = st;
        g_cursor[i] = st;
        g_rowend[i] = st + v;
    }
}

// ---------------- kernel 5: CSR scatter + normalized edge weights ----------------
__global__ void k_csr(const void* ei, const float* __restrict__ w) {
    int e = blockIdx.x * blockDim.x + threadIdx.x;
    if (e >= N_EDGES) return;
    int r = edge_idx(ei, e);
    int c = edge_idx(ei, N_EDGES + e);
    int p = atomicAdd(&g_cursor[r], 1);
    g_ecol[p] = c;
    g_elw[p] = -w[e] * g_dinv[r] * g_dinv[c];
}

// ---------------- mma.sync bf16-split GEMM: 128 rows x 128 cols x K=128 per CTA ----
// A = [src0 | src1] (f32, split to bf16 hi/lo). B = mats wb+2*by+{0,1} of g_Wbhi/lo.
__global__ void __launch_bounds__(256, 1) k_mgemm(
    const float* __restrict__ src0, const float* __restrict__ src1x, int use_rhb,
    int wb, int dst_sel, int ldc) {
    extern __shared__ char sm[];
    const int AH = 0, AL = 32768, BH = 65536, BL = 98304;  // each 128 x 256B
    const int tid = threadIdx.x;
    const int lane = tid & 31, w = tid >> 5;
    const int rowBase = blockIdx.x * 128;
    const float* src1 = use_rhb ? g_rhb : src1x;
    const int matBase = wb + blockIdx.y * 2;

    // ---- load A: thread -> (row = tid&127, source half = tid>>7); 8 chunks of 8 k ----
    {
        int row = tid & 127, half = tid >> 7;
        int gr = rowBase + row;
        const float* s = half ? src1 : src0;
        const float4* sp = (const float4*)(s + (size_t)gr * 64);
        char* ah = sm + AH + row * 256;
        char* al = sm + AL + row * 256;
        int rsw = row & 7;
#pragma unroll
        for (int i = 0; i < 8; i++) {
            float4 v0 = make_float4(0.f, 0.f, 0.f, 0.f), v1 = v0;
            if (gr < N_NODES) { v0 = sp[2 * i]; v1 = sp[2 * i + 1]; }
            int kc = half * 8 + i;
            int off = ((kc ^ rsw) << 4);
            uint4 hi, lo;
            hi.x = pack_bf16x2(v0.x, v0.y); hi.y = pack_bf16x2(v0.z, v0.w);
            hi.z = pack_bf16x2(v1.x, v1.y); hi.w = pack_bf16x2(v1.z, v1.w);
            float rx = v0.x - __bfloat162float(__float2bfloat16(v0.x));
            float ry = v0.y - __bfloat162float(__float2bfloat16(v0.y));
            float rz = v0.z - __bfloat162float(__float2bfloat16(v0.z));
            float rw = v0.w - __bfloat162float(__float2bfloat16(v0.w));
            lo.x = pack_bf16x2(rx, ry); lo.y = pack_bf16x2(rz, rw);
            rx = v1.x - __bfloat162float(__float2bfloat16(v1.x));
            ry = v1.y - __bfloat162float(__float2bfloat16(v1.y));
            rz = v1.z - __bfloat162float(__float2bfloat16(v1.z));
            rw = v1.w - __bfloat162float(__float2bfloat16(v1.w));
            lo.z = pack_bf16x2(rx, ry); lo.w = pack_bf16x2(rz, rw);
            *(uint4*)(ah + off) = hi;
            *(uint4*)(al + off) = lo;
        }
    }
    // ---- load B: 2 mats x 64 n x 16 kc chunks (16B) each, hi+lo ----
#pragma unroll
    for (int j = 0; j < 8; j++) {
        int idx = tid + j * 256;                 // 0..2047
        int mat = idx >> 10, rest = idx & 1023;
        int n = rest >> 4, kc = rest & 15;
        int nn = mat * 64 + n;
        size_t gsi = (size_t)(matBase + mat) * 8192 + n * 128 + kc * 8;
        uint4 hv = *(const uint4*)(g_Wbhi + gsi);
        uint4 lv = *(const uint4*)(g_Wblo + gsi);
        int off = nn * 256 + (((kc ^ (nn & 7))) << 4);
        *(uint4*)(sm + BH + off) = hv;
        *(uint4*)(sm + BL + off) = lv;
    }
    __syncthreads();

    // ---- per-warp tile: rows (w&3)*32, cols (w>>2)*64 ----
    const int Rw = (w & 3) * 32;
    const int NBw = (w >> 2) * 64;
    const uint32_t smb = smem_u32(sm);
    const int tile = lane >> 3, l7 = lane & 7;
    // A ldmatrix lane address pieces
    int a_kbit = tile >> 1;
    int a_row0 = Rw + ((tile & 1) << 3) + l7;        // mt=0
    int a_row1 = a_row0 + 16;                        // mt=1
    uint32_t aBase0 = smb + AH + a_row0 * 256, aSw0 = (uint32_t)(a_row0 & 7);
    uint32_t aBase1 = smb + AH + a_row1 * 256, aSw1 = (uint32_t)(a_row1 & 7);
    // B ldmatrix lane address pieces (per ng)
    int b_kbit = tile & 1;
    int b_nloc = ((tile >> 1) << 3) + l7;
    uint32_t bBase[4], bSw[4];
#pragma unroll
    for (int ng = 0; ng < 4; ng++) {
        int n = NBw + ng * 16 + b_nloc;
        bBase[ng] = smb + BH + n * 256;
        bSw[ng] = (uint32_t)(n & 7);
    }

    float C[2][4][2][4];
#pragma unroll
    for (int a = 0; a < 2; a++)
#pragma unroll
        for (int b = 0; b < 4; b++)
#pragma unroll
            for (int c = 0; c < 2; c++)
#pragma unroll
                for (int d = 0; d < 4; d++) C[a][b][c][d] = 0.f;

#pragma unroll
    for (int ks = 0; ks < 8; ks++) {
        int ks2 = ks * 2;
        uint32_t akc = (uint32_t)((ks2 + a_kbit));
        uint32_t bkc = (uint32_t)((ks2 + b_kbit));
        uint32_t Ah[2][4], Al[2][4];
        ldsm4(Ah[0], aBase0 + ((akc ^ aSw0) << 4));
        ldsm4(Ah[1], aBase1 + ((akc ^ aSw1) << 4));
        ldsm4(Al[0], aBase0 + 32768 + ((akc ^ aSw0) << 4));
        ldsm4(Al[1], aBase1 + 32768 + ((akc ^ aSw1) << 4));
        uint32_t Bh[4][4], Bl[4][4];
#pragma unroll
        for (int ng = 0; ng < 4; ng++) {
            ldsm4(Bh[ng], bBase[ng] + ((bkc ^ bSw[ng]) << 4));
            ldsm4(Bl[ng], bBase[ng] + 32768 + ((bkc ^ bSw[ng]) << 4));
        }
#pragma unroll
        for (int mt = 0; mt < 2; mt++)
#pragma unroll
            for (int ng = 0; ng < 4; ng++) {
                mma_bf16(C[mt][ng][0], Ah[mt], &Bh[ng][0]);
                mma_bf16(C[mt][ng][1], Ah[mt], &Bh[ng][2]);
                mma_bf16(C[mt][ng][0], Ah[mt], &Bl[ng][0]);
                mma_bf16(C[mt][ng][1], Ah[mt], &Bl[ng][2]);
                mma_bf16(C[mt][ng][0], Al[mt], &Bh[ng][0]);
                mma_bf16(C[mt][ng][1], Al[mt], &Bh[ng][2]);
            }
    }

    // ---- epilogue: direct f32 stores ----
    {
        float* Cg = dst_sel ? g_V : g_U;
        int colBase = blockIdx.y * 128 + NBw;
        int q = lane >> 2, tg = lane & 3;
#pragma unroll
        for (int mt = 0; mt < 2; mt++) {
            int r0 = rowBase + Rw + mt * 16 + q;
#pragma unroll
            for (int ng = 0; ng < 4; ng++)
#pragma unroll
                for (int sub = 0; sub < 2; sub++) {
                    int col = colBase + ng * 16 + sub * 8 + tg * 2;
                    float* d0 = &Cg[(size_t)r0 * ldc + col];
                    if (r0 < N_NODES)
                        *(float2*)d0 = make_float2(C[mt][ng][sub][0], C[mt][ng][sub][1]);
                    if (r0 + 8 < N_NODES)
                        *(float2*)(d0 + 8 * ldc) = make_float2(C[mt][ng][sub][2], C[mt][ng][sub][3]);
                }
        }
    }
}

// ---------------- prop1: warp/row over CSR, 128 gathered channels; fused gates ----------------
__global__ void k_prop1(const float* __restrict__ h,
                        const float* __restrict__ bz, const float* __restrict__ br) {
    int gw = (blockIdx.x * blockDim.x + threadIdx.x) >> 5;
    int lane = threadIdx.x & 31;
    if (gw >= N_NODES) return;
    int s = g_rowoff[gw], e = g_rowend[gw];
    int co = lane * 2;
    float a1x = 0.f, a1y = 0.f, a2x = 0.f, a2y = 0.f;
    for (int i = s; i < e; i++) {
        int c = g_ecol[i];
        float w = g_elw[i];
        const float* up = &g_U[c * 256 + co];
        float2 u1 = *(const float2*)(up + 64);
        float2 u2 = *(const float2*)(up + 192);
        a1x += w * u1.x; a1y += w * u1.y;
        a2x += w * u2.x; a2y += w * u2.y;
    }
    const float* rowp = &g_U[gw * 256 + co];
    float2 z0 = *(const float2*)(rowp);
    float2 r0 = *(const float2*)(rowp + 128);
    float2 bz2 = *(const float2*)&bz[co];
    float2 br2 = *(const float2*)&br[co];
    float zx = 1.f / (1.f + __expf(-(z0.x + bz2.x + a1x)));
    float zy = 1.f / (1.f + __expf(-(z0.y + bz2.y + a1y)));
    float rx = 1.f / (1.f + __expf(-(r0.x + br2.x + a2x)));
    float ry = 1.f / (1.f + __expf(-(r0.y + br2.y + a2y)));
    float2 hh = *(const float2*)&h[gw * 64 + co];
    *(float2*)&g_zb[gw * 64 + co] = make_float2(zx, zy);
    *(float2*)&g_rhb[gw * 64 + co] = make_float2(rx * hh.x, ry * hh.y);
}

// ---------------- prop2: 64 gathered channels; fused tanh + GRU update ----------------
__global__ void k_prop2(const float* __restrict__ h, const float* __restrict__ bh,
                        float* __restrict__ out) {
    int gw = (blockIdx.x * blockDim.x + threadIdx.x) >> 5;
    int lane = threadIdx.x & 31;
    if (gw >= N_NODES) return;
    int s = g_rowoff[gw], e = g_rowend[gw];
    int co = lane * 2;
    float ax = 0.f, ay = 0.f;
    for (int i = s; i < e; i++) {
        int c = g_ecol[i];
        float w = g_elw[i];
        float2 u = *(const float2*)&g_V[c * 128 + 64 + co];
        ax += w * u.x; ay += w * u.y;
    }
    float2 h0 = *(const float2*)&g_V[gw * 128 + co];
    float2 bh2 = *(const float2*)&bh[co];
    float htx = tanhf(h0.x + bh2.x + ax);
    float hty = tanhf(h0.y + bh2.y + ay);
    float2 z = *(const float2*)&g_zb[gw * 64 + co];
    float2 hh = *(const float2*)&h[gw * 64 + co];
    float ox = (1.f - z.x) * hh.x + z.x * htx;
    float oy = (1.f - z.y) * hh.y + z.y * hty;
    *(float2*)&out[gw * 64 + co] = make_float2(ox, oy);
}

// ---------------- launch ----------------
extern "C" void kernel_launch(void* const* d_in, const int* in_sizes, int n_in,
                              void* d_out, int out_size) {
    const float* x  = (const float*)d_in[0];
    const void*  ei = d_in[1];
    const float* ew = (const float*)d_in[2];
    const float* h  = (const float*)d_in[3];
    const float* Wz = (const float*)d_in[4];
    const float* bz = (const float*)d_in[5];
    const float* Wr = (const float*)d_in[6];
    const float* br = (const float*)d_in[7];
    const float* Wh = (const float*)d_in[8];
    const float* bh = (const float*)d_in[9];
    float* out = (float*)d_out;

    const int TB = 256;
    const int nb_nodes = (N_NODES + TB - 1) / TB;
    const int nb_edges = (N_EDGES + TB - 1) / TB;
    const int nb_rows  = (N_NODES + 7) / 8;        // 8 warps/block, 1 warp/row
    const int nb_tile  = (N_NODES + 127) / 128;    // 391

    const int SMEM_GEMM = 131072;
    cudaFuncSetAttribute(k_mgemm, cudaFuncAttributeMaxDynamicSharedMemorySize, SMEM_GEMM);

    k_wprep<<<192, TB>>>(Wz, Wr, Wh);
    k_init<<<nb_nodes, TB>>>(ei);
    k_deg<<<nb_edges, TB>>>(ei, ew);
    k_dinv<<<nb_nodes, TB>>>();
    k_blockscan<<<nb_nodes, TB>>>();
    k_csr<<<nb_edges, TB>>>(ei, ew);

    // GEMM1: [x|h] @ {Wz[0],Wz[1] | Wr[0],Wr[1]} -> g_U [N,256]
    k_mgemm<<<dim3(nb_tile, 2), TB, SMEM_GEMM>>>(x, h, 0, /*wb=*/0, /*dst=*/0, /*ldc=*/256);
    k_prop1<<<nb_rows, TB>>>(h, bz, br);

    // GEMM2: [x|r*h] @ {Wh[0],Wh[1]} -> g_V [N,128]
    k_mgemm<<<dim3(nb_tile, 1), TB, SMEM_GEMM>>>(x, nullptr, 1, /*wb=*/4, /*dst=*/1, /*ldc=*/128);
    k_prop2<<<nb_rows, TB>>>(h, bh, out);
}

// round 5
// speedup vs baseline: 1.8294x; 1.0557x over previous
#include <cuda_runtime.h>
#include <cuda_bf16.h>
#include <cuda_fp16.h>
#include <cstdint>

#define N_NODES 50000
#define N_EDGES 800000

// ---------------- scratch (static device globals; no allocation) ----------------
__device__ float g_deg[N_NODES];
__device__ float g_dinv[N_NODES];
__device__ int   g_hist[N_NODES];
__device__ int   g_rowoff[N_NODES];
__device__ int   g_rowend[N_NODES];
__device__ int   g_cursor[N_NODES];
__device__ int   g_ecol[N_EDGES];
__device__ float g_elw[N_EDGES];
__device__ float g_Us[N_NODES * 128];   // f32 self channels [Z0 | R0]
__device__ __half g_Ug[N_NODES * 128];  // fp16 gathered channels [U1 | U2]
__device__ float g_Vs[N_NODES * 64];    // f32 self [H0]
__device__ __half g_Vg[N_NODES * 64];   // fp16 gathered [U3]
__device__ float g_zb[N_NODES * 64];
__device__ float g_rhb[N_NODES * 64];
__device__ __nv_bfloat16 g_Wbhi[6 * 64 * 128];  // [mat][n][k] transposed weights, bf16 hi
__device__ __nv_bfloat16 g_Wblo[6 * 64 * 128];  // bf16 residual
__device__ int   g_is64;
__device__ int   g_counter;

// ---------------- helpers ----------------
__device__ __forceinline__ uint32_t smem_u32(const void* p) {
    uint32_t a;
    asm("{ .reg .u64 t; cvta.to.shared.u64 t, %1; cvt.u32.u64 %0, t; }" : "=r"(a) : "l"(p));
    return a;
}
__device__ __forceinline__ uint32_t pack_bf16x2(float lo, float hi) {
    __nv_bfloat162 t = __floats2bfloat162_rn(lo, hi);
    return *(uint32_t*)&t;
}
__device__ __forceinline__ void ldsm4(uint32_t a[4], uint32_t addr) {
    asm volatile("ldmatrix.sync.aligned.m8n8.x4.shared.b16 {%0,%1,%2,%3}, [%4];"
                 : "=r"(a[0]), "=r"(a[1]), "=r"(a[2]), "=r"(a[3]) : "r"(addr));
}
__device__ __forceinline__ void mma_bf16(float c[4], const uint32_t a[4], const uint32_t b[2]) {
    asm volatile("mma.sync.aligned.m16n8k16.row.col.f32.bf16.bf16.f32 "
                 "{%0,%1,%2,%3}, {%4,%5,%6,%7}, {%8,%9}, {%0,%1,%2,%3};"
                 : "+f"(c[0]), "+f"(c[1]), "+f"(c[2]), "+f"(c[3])
                 : "r"(a[0]), "r"(a[1]), "r"(a[2]), "r"(a[3]), "r"(b[0]), "r"(b[1]));
}
__device__ __forceinline__ int edge_idx(const void* ei, int pos) {
    if (g_is64) return (int)((const long long*)ei)[pos];
    return ((const int*)ei)[pos];
}

// ---------------- kernel 1: zero accumulators + sniff index dtype ----------------
__global__ void k_init(const void* ei) {
    int i = blockIdx.x * blockDim.x + threadIdx.x;
    if (i < N_NODES) { g_deg[i] = 0.f; g_hist[i] = 0; }
    if (i == 0) {
        g_counter = 0;
        const int* p = (const int*)ei;
        int nz = 0;
#pragma unroll 8
        for (int j = 0; j < 256; j++) nz |= p[2 * j + 1];
        g_is64 = (nz == 0) ? 1 : 0;
    }
}

// ---------------- weight prep: transpose + split to bf16 hi/lo ----------------
__global__ void k_wprep(const float* __restrict__ Wz, const float* __restrict__ Wr,
                        const float* __restrict__ Wh) {
    int id = blockIdx.x * 256 + threadIdx.x;
    if (id >= 6 * 8192) return;
    int m = id >> 13;
    int r = id & 8191;
    int n = r >> 7;
    int k = r & 127;
    const float* W = (m < 2) ? Wz : (m < 4) ? Wr : Wh;
    float v = W[(m & 1) * 8192 + k * 64 + n];
    __nv_bfloat16 hi = __float2bfloat16(v);
    g_Wbhi[id] = hi;
    g_Wblo[id] = __float2bfloat16(v - __bfloat162float(hi));
}

// ---------------- kernel 2: degree + histogram ----------------
__global__ void k_deg(const void* ei, const float* __restrict__ w) {
    int e = blockIdx.x * blockDim.x + threadIdx.x;
    if (e >= N_EDGES) return;
    int r = edge_idx(ei, e);
    atomicAdd(&g_deg[r], w[e]);
    atomicAdd(&g_hist[r], 1);
}

// ---------------- kernel 3: dinv + unordered segment assignment (merged) ----------------
__global__ void k_blockscan() {
    int i = blockIdx.x * 256 + threadIdx.x;
    int lane = threadIdx.x & 31, w = threadIdx.x >> 5;
    if (i < N_NODES) {
        float d = g_deg[i];
        g_dinv[i] = (d > 0.f) ? rsqrtf(d) : 0.f;
    }
    int v = (i < N_NODES) ? g_hist[i] : 0;
    int s = v;
#pragma unroll
    for (int o = 1; o < 32; o <<= 1) {
        int t = __shfl_up_sync(0xFFFFFFFFu, s, o);
        if (lane >= o) s += t;
    }
    __shared__ int wsum[8];
    __shared__ int base;
    if (lane == 31) wsum[w] = s;
    __syncthreads();
    if (w == 0 && lane < 8) {
        int t = wsum[lane];
#pragma unroll
        for (int o = 1; o < 8; o <<= 1) {
            int u = __shfl_up_sync(0xFFu, t, o);
            if (lane >= o) t += u;
        }
        wsum[lane] = t;
        if (lane == 7) base = atomicAdd(&g_counter, t);
    }
    __syncthreads();
    int excl = s - v + ((w > 0) ? wsum[w - 1] : 0);
    if (i < N_NODES) {
        int st = base + excl;
        g_rowoff[i] = st;
        g_cursor[i] = st;
        g_rowend[i] = st + v;
    }
}

// ---------------- kernel 5: CSR scatter + normalized edge weights ----------------
__global__ void k_csr(const void* ei, const float* __restrict__ w) {
    int e = blockIdx.x * blockDim.x + threadIdx.x;
    if (e >= N_EDGES) return;
    int r = edge_idx(ei, e);
    int c = edge_idx(ei, N_EDGES + e);
    int p = atomicAdd(&g_cursor[r], 1);
    g_ecol[p] = c;
    g_elw[p] = -w[e] * g_dinv[r] * g_dinv[c];
}

// ---------------- mma.sync bf16-split GEMM: 128 rows x 128 cols x K=128 per CTA ----
// A = [src0 | src1] (f32, split to bf16 hi/lo). B = mats wb+2*by+{0,1} of g_Wbhi/lo.
// mat0 (cols 0-63) -> f32 self buffer; mat1 (cols 64-127) -> fp16 gathered buffer.
__global__ void __launch_bounds__(256, 1) k_mgemm(
    const float* __restrict__ src0, const float* __restrict__ src1x, int use_rhb,
    int wb, int dst_sel) {
    extern __shared__ char sm[];
    const int AH = 0, AL = 32768, BH = 65536, BL = 98304;  // each 128 x 256B
    const int tid = threadIdx.x;
    const int lane = tid & 31, w = tid >> 5;
    const int rowBase = blockIdx.x * 128;
    const float* src1 = use_rhb ? g_rhb : src1x;
    const int matBase = wb + blockIdx.y * 2;

    // ---- load A: thread -> (row = tid&127, source half = tid>>7); 8 chunks of 8 k ----
    {
        int row = tid & 127, half = tid >> 7;
        int gr = rowBase + row;
        const float* s = half ? src1 : src0;
        const float4* sp = (const float4*)(s + (size_t)gr * 64);
        char* ah = sm + AH + row * 256;
        char* al = sm + AL + row * 256;
        int rsw = row & 7;
#pragma unroll
        for (int i = 0; i < 8; i++) {
            float4 v0 = make_float4(0.f, 0.f, 0.f, 0.f), v1 = v0;
            if (gr < N_NODES) { v0 = sp[2 * i]; v1 = sp[2 * i + 1]; }
            int kc = half * 8 + i;
            int off = ((kc ^ rsw) << 4);
            uint4 hi, lo;
            hi.x = pack_bf16x2(v0.x, v0.y); hi.y = pack_bf16x2(v0.z, v0.w);
            hi.z = pack_bf16x2(v1.x, v1.y); hi.w = pack_bf16x2(v1.z, v1.w);
            float rx = v0.x - __bfloat162float(__float2bfloat16(v0.x));
            float ry = v0.y - __bfloat162float(__float2bfloat16(v0.y));
            float rz = v0.z - __bfloat162float(__float2bfloat16(v0.z));
            float rw = v0.w - __bfloat162float(__float2bfloat16(v0.w));
            lo.x = pack_bf16x2(rx, ry); lo.y = pack_bf16x2(rz, rw);
            rx = v1.x - __bfloat162float(__float2bfloat16(v1.x));
            ry = v1.y - __bfloat162float(__float2bfloat16(v1.y));
            rz = v1.z - __bfloat162float(__float2bfloat16(v1.z));
            rw = v1.w - __bfloat162float(__float2bfloat16(v1.w));
            lo.z = pack_bf16x2(rx, ry); lo.w = pack_bf16x2(rz, rw);
            *(uint4*)(ah + off) = hi;
            *(uint4*)(al + off) = lo;
        }
    }
    // ---- load B: 2 mats x 64 n x 16 kc chunks (16B) each, hi+lo ----
#pragma unroll
    for (int j = 0; j < 8; j++) {
        int idx = tid + j * 256;                 // 0..2047
        int mat = idx >> 10, rest = idx & 1023;
        int n = rest >> 4, kc = rest & 15;
        int nn = mat * 64 + n;
        size_t gsi = (size_t)(matBase + mat) * 8192 + n * 128 + kc * 8;
        uint4 hv = *(const uint4*)(g_Wbhi + gsi);
        uint4 lv = *(const uint4*)(g_Wblo + gsi);
        int off = nn * 256 + (((kc ^ (nn & 7))) << 4);
        *(uint4*)(sm + BH + off) = hv;
        *(uint4*)(sm + BL + off) = lv;
    }
    __syncthreads();

    // ---- per-warp tile: rows (w&3)*32, cols (w>>2)*64 ----
    const int Rw = (w & 3) * 32;
    const int matSel = w >> 2;
    const int NBw = matSel * 64;
    const uint32_t smb = smem_u32(sm);
    const int tile = lane >> 3, l7 = lane & 7;
    int a_kbit = tile >> 1;
    int a_row0 = Rw + ((tile & 1) << 3) + l7;        // mt=0
    int a_row1 = a_row0 + 16;                        // mt=1
    uint32_t aBase0 = smb + AH + a_row0 * 256, aSw0 = (uint32_t)(a_row0 & 7);
    uint32_t aBase1 = smb + AH + a_row1 * 256, aSw1 = (uint32_t)(a_row1 & 7);
    int b_kbit = tile & 1;
    int b_nloc = ((tile >> 1) << 3) + l7;
    uint32_t bBase[4], bSw[4];
#pragma unroll
    for (int ng = 0; ng < 4; ng++) {
        int n = NBw + ng * 16 + b_nloc;
        bBase[ng] = smb + BH + n * 256;
        bSw[ng] = (uint32_t)(n & 7);
    }

    float C[2][4][2][4];
#pragma unroll
    for (int a = 0; a < 2; a++)
#pragma unroll
        for (int b = 0; b < 4; b++)
#pragma unroll
            for (int c = 0; c < 2; c++)
#pragma unroll
                for (int d = 0; d < 4; d++) C[a][b][c][d] = 0.f;

#pragma unroll
    for (int ks = 0; ks < 8; ks++) {
        int ks2 = ks * 2;
        uint32_t akc = (uint32_t)((ks2 + a_kbit));
        uint32_t bkc = (uint32_t)((ks2 + b_kbit));
        uint32_t Ah[2][4], Al[2][4];
        ldsm4(Ah[0], aBase0 + ((akc ^ aSw0) << 4));
        ldsm4(Ah[1], aBase1 + ((akc ^ aSw1) << 4));
        ldsm4(Al[0], aBase0 + 32768 + ((akc ^ aSw0) << 4));
        ldsm4(Al[1], aBase1 + 32768 + ((akc ^ aSw1) << 4));
        uint32_t Bh[4][4], Bl[4][4];
#pragma unroll
        for (int ng = 0; ng < 4; ng++) {
            ldsm4(Bh[ng], bBase[ng] + ((bkc ^ bSw[ng]) << 4));
            ldsm4(Bl[ng], bBase[ng] + 32768 + ((bkc ^ bSw[ng]) << 4));
        }
#pragma unroll
        for (int mt = 0; mt < 2; mt++)
#pragma unroll
            for (int ng = 0; ng < 4; ng++) {
                mma_bf16(C[mt][ng][0], Ah[mt], &Bh[ng][0]);
                mma_bf16(C[mt][ng][1], Ah[mt], &Bh[ng][2]);
                mma_bf16(C[mt][ng][0], Ah[mt], &Bl[ng][0]);
                mma_bf16(C[mt][ng][1], Ah[mt], &Bl[ng][2]);
                mma_bf16(C[mt][ng][0], Al[mt], &Bh[ng][0]);
                mma_bf16(C[mt][ng][1], Al[mt], &Bh[ng][2]);
            }
    }

    // ---- epilogue: mat0 -> f32 self buffer, mat1 -> fp16 gathered buffer ----
    {
        int ldS = dst_sel ? 64 : 128;                 // f32 / half buffers share ld
        float* fdst = dst_sel ? g_Vs : g_Us;
        __half* hdst = dst_sel ? g_Vg : g_Ug;
        int colBase = blockIdx.y * 64;                // by=0 for GEMM2
        int q = lane >> 2, tg = lane & 3;
#pragma unroll
        for (int mt = 0; mt < 2; mt++) {
            int r0 = rowBase + Rw + mt * 16 + q;
#pragma unroll
            for (int ng = 0; ng < 4; ng++)
#pragma unroll
                for (int sub = 0; sub < 2; sub++) {
                    int col = colBase + ng * 16 + sub * 8 + tg * 2;
                    if (matSel == 0) {
                        float* d0 = &fdst[(size_t)r0 * ldS + col];
                        if (r0 < N_NODES)
                            *(float2*)d0 = make_float2(C[mt][ng][sub][0], C[mt][ng][sub][1]);
                        if (r0 + 8 < N_NODES)
                            *(float2*)(d0 + 8 * ldS) = make_float2(C[mt][ng][sub][2], C[mt][ng][sub][3]);
                    } else {
                        __half* d0 = &hdst[(size_t)r0 * ldS + col];
                        if (r0 < N_NODES)
                            *(__half2*)d0 = __floats2half2_rn(C[mt][ng][sub][0], C[mt][ng][sub][1]);
                        if (r0 + 8 < N_NODES)
                            *(__half2*)(d0 + 8 * ldS) = __floats2half2_rn(C[mt][ng][sub][2], C[mt][ng][sub][3]);
                    }
                }
        }
    }
}

// ---------------- prop1: warp/row over CSR, fp16 gathers; fused gates ----------------
__global__ void k_prop1(const float* __restrict__ h,
                        const float* __restrict__ bz, const float* __restrict__ br) {
    int gw = (blockIdx.x * blockDim.x + threadIdx.x) >> 5;
    int lane = threadIdx.x & 31;
    if (gw >= N_NODES) return;
    int s = g_rowoff[gw], e = g_rowend[gw];
    int co = lane * 2;
    float a1x = 0.f, a1y = 0.f, a2x = 0.f, a2y = 0.f;
    for (int i = s; i < e; i++) {
        int c = g_ecol[i];
        float w = g_elw[i];
        const __half2* up = (const __half2*)&g_Ug[(size_t)c * 128];
        float2 u1 = __half22float2(up[lane]);
        float2 u2 = __half22float2(up[32 + lane]);
        a1x += w * u1.x; a1y += w * u1.y;
        a2x += w * u2.x; a2y += w * u2.y;
    }
    const float* rowp = &g_Us[(size_t)gw * 128 + co];
    float2 z0 = *(const float2*)(rowp);
    float2 r0 = *(const float2*)(rowp + 64);
    float2 bz2 = *(const float2*)&bz[co];
    float2 br2 = *(const float2*)&br[co];
    float zx = 1.f / (1.f + __expf(-(z0.x + bz2.x + a1x)));
    float zy = 1.f / (1.f + __expf(-(z0.y + bz2.y + a1y)));
    float rx = 1.f / (1.f + __expf(-(r0.x + br2.x + a2x)));
    float ry = 1.f / (1.f + __expf(-(r0.y + br2.y + a2y)));
    float2 hh = *(const float2*)&h[gw * 64 + co];
    *(float2*)&g_zb[gw * 64 + co] = make_float2(zx, zy);
    *(float2*)&g_rhb[gw * 64 + co] = make_float2(rx * hh.x, ry * hh.y);
}

// ---------------- prop2: fp16 gathers; fused tanh + GRU update ----------------
__global__ void k_prop2(const float* __restrict__ h, const float* __restrict__ bh,
                        float* __restrict__ out) {
    int gw = (blockIdx.x * blockDim.x + threadIdx.x) >> 5;
    int lane = threadIdx.x & 31;
    if (gw >= N_NODES) return;
    int s = g_rowoff[gw], e = g_rowend[gw];
    int co = lane * 2;
    float ax = 0.f, ay = 0.f;
    for (int i = s; i < e; i++) {
        int c = g_ecol[i];
        float w = g_elw[i];
        float2 u = __half22float2(((const __half2*)&g_Vg[(size_t)c * 64])[lane]);
        ax += w * u.x; ay += w * u.y;
    }
    float2 h0 = *(const float2*)&g_Vs[(size_t)gw * 64 + co];
    float2 bh2 = *(const float2*)&bh[co];
    float htx = tanhf(h0.x + bh2.x + ax);
    float hty = tanhf(h0.y + bh2.y + ay);
    float2 z = *(const float2*)&g_zb[gw * 64 + co];
    float2 hh = *(const float2*)&h[gw * 64 + co];
    float ox = (1.f - z.x) * hh.x + z.x * htx;
    float oy = (1.f - z.y) * hh.y + z.y * hty;
    *(float2*)&out[gw * 64 + co] = make_float2(ox, oy);
}

// ---------------- launch ----------------
extern "C" void kernel_launch(void* const* d_in, const int* in_sizes, int n_in,
                              void* d_out, int out_size) {
    const float* x  = (const float*)d_in[0];
    const void*  ei = d_in[1];
    const float* ew = (const float*)d_in[2];
    const float* h  = (const float*)d_in[3];
    const float* Wz = (const float*)d_in[4];
    const float* bz = (const float*)d_in[5];
    const float* Wr = (const float*)d_in[6];
    const float* br = (const float*)d_in[7];
    const float* Wh = (const float*)d_in[8];
    const float* bh = (const float*)d_in[9];
    float* out = (float*)d_out;

    const int TB = 256;
    const int nb_nodes = (N_NODES + TB - 1) / TB;
    const int nb_edges = (N_EDGES + TB - 1) / TB;
    const int nb_rows  = (N_NODES + 7) / 8;        // 8 warps/block, 1 warp/row
    const int nb_tile  = (N_NODES + 127) / 128;    // 391

    const int SMEM_GEMM = 131072;
    cudaFuncSetAttribute(k_mgemm, cudaFuncAttributeMaxDynamicSharedMemorySize, SMEM_GEMM);

    k_wprep<<<192, TB>>>(Wz, Wr, Wh);
    k_init<<<nb_nodes, TB>>>(ei);
    k_deg<<<nb_edges, TB>>>(ei, ew);
    k_blockscan<<<nb_nodes, TB>>>();
    k_csr<<<nb_edges, TB>>>(ei, ew);

    // GEMM1: [x|h] @ {Wz[0],Wz[1] | Wr[0],Wr[1]} -> g_Us/g_Ug
    k_mgemm<<<dim3(nb_tile, 2), TB, SMEM_GEMM>>>(x, h, 0, /*wb=*/0, /*dst=*/0);
    k_prop1<<<nb_rows, TB>>>(h, bz, br);

    // GEMM2: [x|r*h] @ {Wh[0],Wh[1]} -> g_Vs/g_Vg
    k_mgemm<<<dim3(nb_tile, 1), TB, SMEM_GEMM>>>(x, nullptr, 1, /*wb=*/4, /*dst=*/1);
    k_prop2<<<nb_rows, TB>>>(h, bh, out);
}